// round 3
// baseline (speedup 1.0000x reference)
#include <cuda_runtime.h>
#include <stdint.h>

#define N_RES 1024
#define C_M   256
#define C_Z   128
#define NUM_BINS 15
#define EPS 1e-5f
#define INF_F 1e8f

// ---------------------------------------------------------------------------
// Kernel 1: m_update = LayerNorm(m)   [1024, 256]
// One warp per row; each lane handles 2 float4 (8 floats) of the 256.
// ---------------------------------------------------------------------------
__global__ void __launch_bounds__(256) m_ln_kernel(
        const float* __restrict__ m,
        const float* __restrict__ w,
        const float* __restrict__ b,
        float* __restrict__ out) {
    int warp = (blockIdx.x * blockDim.x + threadIdx.x) >> 5;
    int lane = threadIdx.x & 31;
    if (warp >= N_RES) return;

    const float4* row = reinterpret_cast<const float4*>(m + (size_t)warp * C_M);
    float4 v0 = row[lane];
    float4 v1 = row[lane + 32];

    float s  = v0.x + v0.y + v0.z + v0.w + v1.x + v1.y + v1.z + v1.w;
    float ss = v0.x*v0.x + v0.y*v0.y + v0.z*v0.z + v0.w*v0.w
             + v1.x*v1.x + v1.y*v1.y + v1.z*v1.z + v1.w*v1.w;

    #pragma unroll
    for (int off = 16; off > 0; off >>= 1) {
        s  += __shfl_xor_sync(0xFFFFFFFFu, s,  off);
        ss += __shfl_xor_sync(0xFFFFFFFFu, ss, off);
    }

    float mu   = s * (1.0f / C_M);
    float var  = ss * (1.0f / C_M) - mu * mu;
    float rstd = rsqrtf(var + EPS);

    const float4* wv = reinterpret_cast<const float4*>(w);
    const float4* bv = reinterpret_cast<const float4*>(b);
    float4 w0 = wv[lane], w1 = wv[lane + 32];
    float4 b0 = bv[lane], b1 = bv[lane + 32];

    float4 o0, o1;
    o0.x = (v0.x - mu) * rstd * w0.x + b0.x;
    o0.y = (v0.y - mu) * rstd * w0.y + b0.y;
    o0.z = (v0.z - mu) * rstd * w0.z + b0.z;
    o0.w = (v0.w - mu) * rstd * w0.w + b0.w;
    o1.x = (v1.x - mu) * rstd * w1.x + b1.x;
    o1.y = (v1.y - mu) * rstd * w1.y + b1.y;
    o1.z = (v1.z - mu) * rstd * w1.z + b1.z;
    o1.w = (v1.w - mu) * rstd * w1.w + b1.w;

    float4* orow = reinterpret_cast<float4*>(out + (size_t)warp * C_M);
    orow[lane]      = o0;
    orow[lane + 32] = o1;
}

// ---------------------------------------------------------------------------
// Kernel 2: z_update = LayerNorm(z) + distogram_linear(x)   [1024,1024,128]
// One warp per TWO consecutive (i,j) pairs (same i). Front-batched loads
// (MLP=2 per lane). 1 KB load + 1 KB store per warp, fully coalesced.
// Distogram: one-hot over 15 disjoint bins -> select one column of lin_w.
// ---------------------------------------------------------------------------
__global__ void __launch_bounds__(256) z_kernel(
        const float* __restrict__ z,
        const float* __restrict__ x,
        const float* __restrict__ w,
        const float* __restrict__ b,
        const float* __restrict__ lin_w,   // [C_Z, NUM_BINS]
        const float* __restrict__ lin_b,   // [C_Z]
        float* __restrict__ out) {
    int warp = (blockIdx.x * blockDim.x + threadIdx.x) >> 5;  // 0 .. 524287
    int lane = threadIdx.x & 31;

    // Each warp handles rows r0 = 2*warp and r0+1 (consecutive j, same i).
    int r0 = warp << 1;
    int i  = r0 >> 10;
    int j0 = r0 & (N_RES - 1);
    int j1 = j0 + 1;

    // --- front-batched loads: two z rows, MLP=2 per lane ---
    const float4* zrow0 = reinterpret_cast<const float4*>(z + (size_t)r0 * C_Z);
    const float4* zrow1 = zrow0 + (C_Z / 4);
    float4 va = zrow0[lane];
    float4 vb = zrow1[lane];

    // --- warp reductions for both rows (interleaved shuffles) ---
    float sa  = va.x + va.y + va.z + va.w;
    float ssa = va.x*va.x + va.y*va.y + va.z*va.z + va.w*va.w;
    float sb  = vb.x + vb.y + vb.z + vb.w;
    float ssb = vb.x*vb.x + vb.y*vb.y + vb.z*vb.z + vb.w*vb.w;
    #pragma unroll
    for (int off = 16; off > 0; off >>= 1) {
        sa  += __shfl_xor_sync(0xFFFFFFFFu, sa,  off);
        ssa += __shfl_xor_sync(0xFFFFFFFFu, ssa, off);
        sb  += __shfl_xor_sync(0xFFFFFFFFu, sb,  off);
        ssb += __shfl_xor_sync(0xFFFFFFFFu, ssb, off);
    }
    float mua   = sa * (1.0f / C_Z);
    float rstda = rsqrtf(ssa * (1.0f / C_Z) - mua * mua + EPS);
    float mub   = sb * (1.0f / C_Z);
    float rstdb = rsqrtf(ssb * (1.0f / C_Z) - mub * mub + EPS);

    // --- squared pairwise distances (x resident in L1/L2) ---
    float xi0 = __ldg(x + 3*i + 0), xi1 = __ldg(x + 3*i + 1), xi2 = __ldg(x + 3*i + 2);
    float xa0 = __ldg(x + 3*j0 + 0), xa1 = __ldg(x + 3*j0 + 1), xa2 = __ldg(x + 3*j0 + 2);
    float xb0 = __ldg(x + 3*j1 + 0), xb1 = __ldg(x + 3*j1 + 1), xb2 = __ldg(x + 3*j1 + 2);
    float dax = xi0 - xa0, day = xi1 - xa1, daz = xi2 - xa2;
    float dbx = xi0 - xb0, dby = xi1 - xb1, dbz = xi2 - xb2;
    float d2a = dax*dax + day*day + daz*daz;
    float d2b = dbx*dbx + dby*dby + dbz*dbz;

    // --- bin search: bins = 3.25 + 1.25*k (compile-time constants) ---
    int bina = -1, binb = -1;
    #pragma unroll
    for (int k = 0; k < NUM_BINS; k++) {
        float lo = 3.25f + 1.25f * k;
        lo = lo * lo;
        float hik = 3.25f + 1.25f * (k + 1);
        float hi = (k < NUM_BINS - 1) ? hik * hik : INF_F;
        if (d2a > lo && d2a < hi) bina = k;
        if (d2b > lo && d2b < hi) binb = k;
    }

    // --- shared per-channel params (loaded once for both rows) ---
    float4 wr = reinterpret_cast<const float4*>(w)[lane];
    float4 br = reinterpret_cast<const float4*>(b)[lane];
    float4 lb = reinterpret_cast<const float4*>(lin_b)[lane];

    int c = lane * 4;
    float aa0 = lb.x, aa1 = lb.y, aa2 = lb.z, aa3 = lb.w;
    if (bina >= 0) {
        aa0 += __ldg(lin_w + (c + 0) * NUM_BINS + bina);
        aa1 += __ldg(lin_w + (c + 1) * NUM_BINS + bina);
        aa2 += __ldg(lin_w + (c + 2) * NUM_BINS + bina);
        aa3 += __ldg(lin_w + (c + 3) * NUM_BINS + bina);
    }
    float ab0, ab1, ab2, ab3;
    if (binb == bina) {
        // warp-uniform fast path: reuse the gathered column
        ab0 = aa0; ab1 = aa1; ab2 = aa2; ab3 = aa3;
    } else {
        ab0 = lb.x; ab1 = lb.y; ab2 = lb.z; ab3 = lb.w;
        if (binb >= 0) {
            ab0 += __ldg(lin_w + (c + 0) * NUM_BINS + binb);
            ab1 += __ldg(lin_w + (c + 1) * NUM_BINS + binb);
            ab2 += __ldg(lin_w + (c + 2) * NUM_BINS + binb);
            ab3 += __ldg(lin_w + (c + 3) * NUM_BINS + binb);
        }
    }

    float4 oa, ob;
    oa.x = (va.x - mua) * rstda * wr.x + br.x + aa0;
    oa.y = (va.y - mua) * rstda * wr.y + br.y + aa1;
    oa.z = (va.z - mua) * rstda * wr.z + br.z + aa2;
    oa.w = (va.w - mua) * rstda * wr.w + br.w + aa3;
    ob.x = (vb.x - mub) * rstdb * wr.x + br.x + ab0;
    ob.y = (vb.y - mub) * rstdb * wr.y + br.y + ab1;
    ob.z = (vb.z - mub) * rstdb * wr.z + br.z + ab2;
    ob.w = (vb.w - mub) * rstdb * wr.w + br.w + ab3;

    float4* orow0 = reinterpret_cast<float4*>(out + (size_t)r0 * C_Z);
    float4* orow1 = orow0 + (C_Z / 4);
    orow0[lane] = oa;
    orow1[lane] = ob;
}

// ---------------------------------------------------------------------------
// Launch
// Inputs (metadata order): m, z, x, ln_m_w, ln_m_b, ln_z_w, ln_z_b, lin_w, lin_b
// Output: m_update [1024*256] followed by z_update [1024*1024*128]
// ---------------------------------------------------------------------------
extern "C" void kernel_launch(void* const* d_in, const int* in_sizes, int n_in,
                              void* d_out, int out_size) {
    const float* m      = (const float*)d_in[0];
    const float* z      = (const float*)d_in[1];
    const float* x      = (const float*)d_in[2];
    const float* ln_m_w = (const float*)d_in[3];
    const float* ln_m_b = (const float*)d_in[4];
    const float* ln_z_w = (const float*)d_in[5];
    const float* ln_z_b = (const float*)d_in[6];
    const float* lin_w  = (const float*)d_in[7];
    const float* lin_b  = (const float*)d_in[8];

    float* out_m = (float*)d_out;
    float* out_z = out_m + (size_t)N_RES * C_M;

    // m kernel: 1024 warps -> 128 blocks x 256 threads
    m_ln_kernel<<<(N_RES * 32 + 255) / 256, 256>>>(m, ln_m_w, ln_m_b, out_m);

    // z kernel: 524288 warps (2 rows each) -> 65536 blocks x 256 threads
    long long total_warps = ((long long)N_RES * N_RES) / 2;
    int blocks = (int)((total_warps * 32 + 255) / 256);
    z_kernel<<<blocks, 256>>>(z, x, ln_z_w, ln_z_b, lin_w, lin_b, out_z);
}

// round 11
// speedup vs baseline: 1.1254x; 1.1254x over previous
#include <cuda_runtime.h>
#include <stdint.h>

#define N_RES 1024
#define C_M   256
#define C_Z   128
#define NUM_BINS 15
#define EPS 1e-5f
#define INF_F 1e8f

// Scratch: folded add-table (ln_z_b + lin_b + lin_w[:,bin]; row 15 = no bin),
// and packed x coordinates.
__device__ float  g_table[(NUM_BINS + 1) * C_Z];
__device__ float4 g_x4[N_RES];

// ---------------------------------------------------------------------------
// Pre-kernel: blocks 0..127 do LayerNorm(m) (one warp per row);
//             block 128 builds g_table and g_x4.
// ---------------------------------------------------------------------------
__global__ void __launch_bounds__(256) pre_kernel(
        const float* __restrict__ m,
        const float* __restrict__ mw,
        const float* __restrict__ mb,
        const float* __restrict__ x,
        const float* __restrict__ zb,      // ln_z_b
        const float* __restrict__ lin_w,   // [C_Z, NUM_BINS]
        const float* __restrict__ lin_b,   // [C_Z]
        float* __restrict__ out_m) {
    if (blockIdx.x == 128) {
        int tid = threadIdx.x;
        // table: 16*128 = 2048 entries
        for (int idx = tid; idx < (NUM_BINS + 1) * C_Z; idx += 256) {
            int bin = idx >> 7;          // 0..15
            int c   = idx & (C_Z - 1);
            float v = zb[c] + lin_b[c];
            if (bin < NUM_BINS) v += lin_w[c * NUM_BINS + bin];
            g_table[idx] = v;
        }
        // packed x
        for (int n = tid; n < N_RES; n += 256) {
            g_x4[n] = make_float4(x[3*n], x[3*n+1], x[3*n+2], 0.0f);
        }
        return;
    }

    int warp = (blockIdx.x * 256 + threadIdx.x) >> 5;   // 0..1023
    int lane = threadIdx.x & 31;

    const float4* row = reinterpret_cast<const float4*>(m + (size_t)warp * C_M);
    float4 v0 = row[lane];
    float4 v1 = row[lane + 32];

    float s  = v0.x + v0.y + v0.z + v0.w + v1.x + v1.y + v1.z + v1.w;
    float ss = v0.x*v0.x + v0.y*v0.y + v0.z*v0.z + v0.w*v0.w
             + v1.x*v1.x + v1.y*v1.y + v1.z*v1.z + v1.w*v1.w;

    #pragma unroll
    for (int off = 16; off > 0; off >>= 1) {
        s  += __shfl_xor_sync(0xFFFFFFFFu, s,  off);
        ss += __shfl_xor_sync(0xFFFFFFFFu, ss, off);
    }

    float mu   = s * (1.0f / C_M);
    float rstd = rsqrtf(ss * (1.0f / C_M) - mu * mu + EPS);

    const float4* wv = reinterpret_cast<const float4*>(mw);
    const float4* bv = reinterpret_cast<const float4*>(mb);
    float4 w0 = wv[lane], w1 = wv[lane + 32];
    float4 b0 = bv[lane], b1 = bv[lane + 32];

    float4 o0, o1;
    o0.x = (v0.x - mu) * rstd * w0.x + b0.x;
    o0.y = (v0.y - mu) * rstd * w0.y + b0.y;
    o0.z = (v0.z - mu) * rstd * w0.z + b0.z;
    o0.w = (v0.w - mu) * rstd * w0.w + b0.w;
    o1.x = (v1.x - mu) * rstd * w1.x + b1.x;
    o1.y = (v1.y - mu) * rstd * w1.y + b1.y;
    o1.z = (v1.z - mu) * rstd * w1.z + b1.z;
    o1.w = (v1.w - mu) * rstd * w1.w + b1.w;

    float4* orow = reinterpret_cast<float4*>(out_m + (size_t)warp * C_M);
    orow[lane]      = o0;
    orow[lane + 32] = o1;
}

// Exact squared bin boundary (compile-time constants after unroll)
__device__ __forceinline__ float sqb(int k) {
    float b = 3.25f + 1.25f * k;
    return b * b;
}

// Candidate-verified bin: result identical to the reference 15-compare loop.
__device__ __forceinline__ int find_bin(float d2) {
    float t = (sqrtf(d2) - 3.25f) * 0.8f;
    int kc = (int)floorf(t);
    kc = max(0, min(NUM_BINS - 1, kc));
    int bin = -1;
    #pragma unroll
    for (int dk = -1; dk <= 1; dk++) {
        int k = kc + dk;
        if (k >= 0 && k < NUM_BINS) {
            float lo = sqb(k);
            float hi = (k < NUM_BINS - 1) ? sqb(k + 1) : INF_F;
            if (d2 > lo && d2 < hi) bin = k;
        }
    }
    return bin;
}

// ---------------------------------------------------------------------------
// z kernel: one warp per TWO consecutive (i,j) pairs (same i).
// Per-warp l1tex wavefronts: 8 (z ld) + 8 (st) + 4 (w) + 4-8 (table) + 3 (x).
// ---------------------------------------------------------------------------
__global__ void __launch_bounds__(256) z_kernel(
        const float* __restrict__ z,
        const float* __restrict__ w,       // ln_z_w
        float* __restrict__ out) {
    int warp = (blockIdx.x * 256 + threadIdx.x) >> 5;  // 0 .. 524287
    int lane = threadIdx.x & 31;

    int r0 = warp << 1;
    int i  = r0 >> 10;
    int j0 = r0 & (N_RES - 1);

    // front-batched loads (MLP=2 per lane)
    const float4* zrow0 = reinterpret_cast<const float4*>(z + (size_t)r0 * C_Z);
    const float4* zrow1 = zrow0 + (C_Z / 4);
    float4 va = zrow0[lane];
    float4 vb = zrow1[lane];

    // warp-uniform x loads (broadcast)
    float4 xi = g_x4[i];
    float4 xa = g_x4[j0];
    float4 xb = g_x4[j0 + 1];

    // reductions for both rows (interleaved shuffles)
    float sa  = va.x + va.y + va.z + va.w;
    float ssa = va.x*va.x + va.y*va.y + va.z*va.z + va.w*va.w;
    float sb  = vb.x + vb.y + vb.z + vb.w;
    float ssb = vb.x*vb.x + vb.y*vb.y + vb.z*vb.z + vb.w*vb.w;
    #pragma unroll
    for (int off = 16; off > 0; off >>= 1) {
        sa  += __shfl_xor_sync(0xFFFFFFFFu, sa,  off);
        ssa += __shfl_xor_sync(0xFFFFFFFFu, ssa, off);
        sb  += __shfl_xor_sync(0xFFFFFFFFu, sb,  off);
        ssb += __shfl_xor_sync(0xFFFFFFFFu, ssb, off);
    }
    float mua   = sa * (1.0f / C_Z);
    float rstda = rsqrtf(ssa * (1.0f / C_Z) - mua * mua + EPS);
    float mub   = sb * (1.0f / C_Z);
    float rstdb = rsqrtf(ssb * (1.0f / C_Z) - mub * mub + EPS);

    // distances + bins
    float dax = xi.x - xa.x, day = xi.y - xa.y, daz = xi.z - xa.z;
    float dbx = xi.x - xb.x, dby = xi.y - xb.y, dbz = xi.z - xb.z;
    float d2a = dax*dax + day*day + daz*daz;
    float d2b = dbx*dbx + dby*dby + dbz*dbz;
    int bina = find_bin(d2a);
    int binb = find_bin(d2b);
    int idxa = (bina < 0) ? NUM_BINS : bina;
    int idxb = (binb < 0) ? NUM_BINS : binb;

    // folded add-table rows (coalesced float4, L1/L2-resident)
    const float4* tbl = reinterpret_cast<const float4*>(g_table);
    float4 ta = __ldg(&tbl[idxa * (C_Z / 4) + lane]);
    float4 tb = (idxb == idxa) ? ta : __ldg(&tbl[idxb * (C_Z / 4) + lane]);

    float4 wr = __ldg(&reinterpret_cast<const float4*>(w)[lane]);

    float4 oa, ob;
    oa.x = (va.x - mua) * rstda * wr.x + ta.x;
    oa.y = (va.y - mua) * rstda * wr.y + ta.y;
    oa.z = (va.z - mua) * rstda * wr.z + ta.z;
    oa.w = (va.w - mua) * rstda * wr.w + ta.w;
    ob.x = (vb.x - mub) * rstdb * wr.x + tb.x;
    ob.y = (vb.y - mub) * rstdb * wr.y + tb.y;
    ob.z = (vb.z - mub) * rstdb * wr.z + tb.z;
    ob.w = (vb.w - mub) * rstdb * wr.w + tb.w;

    float4* orow0 = reinterpret_cast<float4*>(out + (size_t)r0 * C_Z);
    float4* orow1 = orow0 + (C_Z / 4);
    orow0[lane] = oa;
    orow1[lane] = ob;
}

// ---------------------------------------------------------------------------
// Launch
// Inputs: m, z, x, ln_m_w, ln_m_b, ln_z_w, ln_z_b, lin_w, lin_b
// Output: m_update [1024*256] then z_update [1024*1024*128]
// ---------------------------------------------------------------------------
extern "C" void kernel_launch(void* const* d_in, const int* in_sizes, int n_in,
                              void* d_out, int out_size) {
    const float* m      = (const float*)d_in[0];
    const float* z      = (const float*)d_in[1];
    const float* x      = (const float*)d_in[2];
    const float* ln_m_w = (const float*)d_in[3];
    const float* ln_m_b = (const float*)d_in[4];
    const float* ln_z_w = (const float*)d_in[5];
    const float* ln_z_b = (const float*)d_in[6];
    const float* lin_w  = (const float*)d_in[7];
    const float* lin_b  = (const float*)d_in[8];

    float* out_m = (float*)d_out;
    float* out_z = out_m + (size_t)N_RES * C_M;

    // 128 blocks for m (1024 warps) + 1 block for table/x packing
    pre_kernel<<<129, 256>>>(m, ln_m_w, ln_m_b, x, ln_z_b, lin_w, lin_b, out_m);

    // z kernel: 524288 warps (2 rows each) -> 65536 blocks x 256 threads
    z_kernel<<<65536, 256>>>(z, ln_z_w, out_z);
}